// round 7
// baseline (speedup 1.0000x reference)
#include <cuda_runtime.h>
#include <cuda_bf16.h>
#include <stdint.h>
#include <math.h>

#define B_DIM 8
#define Q_DIM 64
#define N_DIM 8192
#define K_DIM 512
#define C_DIM 256

#define GRID 296               // persistent CTAs (2 per SM)
#define N_VQ_TILES 1024        // (B*N)/64 tiles of 64 n-columns
#define N_REC_TILES 256        // (B*N)/256 tiles of 256 n-columns
#define N_WORK (N_VQ_TILES + N_REC_TILES)   // 1280 = 256 groups of 5 (4 vq + 1 rec)
#define NP N_WORK

__device__ float g_partials[NP];
__device__ int   g_arrived;    // zero-init; reset by finishing block
__device__ int   g_work;       // work-stealing cursor; reset by finishing block

// ---------------- smem layout (bytes) ----------------
// rows padded to 144B (= 9 x 16B): conflict-free ldmatrix AND STS.128
#define EPAD 144
#define SM_RED   0                     // 32B  (8 floats)
#define SM_Z2    32                    // 1024B (4 partial ze2 sums per column)
#define SM_WMIN  1056                  // 2048B (per-warp per-n mins: [8][64])
#define SM_E2    3104                  // 2048B (||emb_k||^2)
#define SM_ZET   5152                  // 64 * 144 = 9216B  (zeT[n][q] bf16)
#define SM_EMB   14368                 // 512 * 144 = 73728B (emb[k][q] bf16)
#define SMEM_TOTAL 88096

// ---------------- helpers ----------------
__device__ __forceinline__ uint32_t smem_u32(const void* p) {
    uint32_t a;
    asm("{ .reg .u64 t; cvta.to.shared.u64 t, %1; cvt.u32.u64 %0, t; }" : "=r"(a) : "l"(p));
    return a;
}

#define LDSM_X4(r0, r1, r2, r3, addr) \
    asm volatile("ldmatrix.sync.aligned.m8n8.x4.shared.b16 {%0,%1,%2,%3}, [%4];" \
                 : "=r"(r0), "=r"(r1), "=r"(r2), "=r"(r3) : "r"(addr))

#define MMA_BF16(a0, a1, a2, a3, b0, b1, c0, c1, c2, c3) \
    asm volatile("mma.sync.aligned.m16n8k16.row.col.f32.bf16.bf16.f32 " \
                 "{%0,%1,%2,%3}, {%4,%5,%6,%7}, {%8,%9}, {%0,%1,%2,%3};" \
                 : "+f"(c0), "+f"(c1), "+f"(c2), "+f"(c3) \
                 : "r"(a0), "r"(a1), "r"(a2), "r"(a3), "r"(b0), "r"(b1))

__device__ __forceinline__ float block_sum8(float v, float* red) {
    #pragma unroll
    for (int off = 16; off > 0; off >>= 1)
        v += __shfl_down_sync(0xFFFFFFFFu, v, off);
    int lane = threadIdx.x & 31;
    int wid  = threadIdx.x >> 5;
    if (lane == 0) red[wid] = v;
    __syncthreads();
    if (wid == 0) {
        v = (lane < 8) ? red[lane] : 0.0f;
        #pragma unroll
        for (int off = 4; off > 0; off >>= 1)
            v += __shfl_down_sync(0xFFFFFFFFu, v, off);
    }
    return v;  // valid in thread 0
}

// Last-arriving block sums all partials in a FIXED order -> bit-deterministic.
__device__ __forceinline__ void finalize(float* out) {
    __shared__ float fr[4];
    __shared__ int last;
    __threadfence();
    if (threadIdx.x == 0)
        last = (atomicAdd(&g_arrived, 1) == GRID - 1);
    __syncthreads();
    if (!last) return;
    __threadfence();
    float s = 0.0f;
    if (threadIdx.x < 128) {
        for (int i = threadIdx.x; i < NP; i += 128)
            s += g_partials[i];
    }
    #pragma unroll
    for (int off = 16; off > 0; off >>= 1)
        s += __shfl_down_sync(0xFFFFFFFFu, s, off);
    if (threadIdx.x < 128 && (threadIdx.x & 31) == 0)
        fr[threadIdx.x >> 5] = s;
    __syncthreads();
    if (threadIdx.x == 0) {
        out[0] = ((fr[0] + fr[1]) + (fr[2] + fr[3]));
        g_arrived = 0;   // reset for next graph replay
        g_work = 0;
    }
}

// ==================== fused persistent kernel ====================
// 256 threads = 8 warps.
// vq tile: warp w owns codewords [64w, 64w+64) and ALL 64 n-rows (4 A-sets).
// rec tile: classic 256-thread logsumexp block.
__global__ __launch_bounds__(256, 2) void fused_kernel(
    const float* __restrict__ ze, const float* __restrict__ emb,
    const float* __restrict__ qp, const int* __restrict__ tw,
    float* __restrict__ out)
{
    extern __shared__ char smem[];
    __shared__ int work_sh;
    const uint32_t sb = smem_u32(smem);
    const int tid  = threadIdx.x;
    const int lane = tid & 31;
    const int wid  = tid >> 5;

    float* red  = (float*)(smem + SM_RED);
    float* z2s  = (float*)(smem + SM_Z2);
    float* wmin = (float*)(smem + SM_WMIN);

    // ---- one-time: emb fp32 (gmem/L2) -> bf16 padded smem + ||emb||^2 ----
    {
        float* e2 = (float*)(smem + SM_E2);
        #pragma unroll
        for (int i = 0; i < K_DIM / 256; i++) {
            int k = tid + 256 * i;
            const float4* src = (const float4*)(emb + (size_t)k * Q_DIM);
            char* dst = smem + SM_EMB + k * EPAD;
            float s = 0.0f;
            #pragma unroll
            for (int j = 0; j < 8; j++) {          // 8 chunks of 16B (8 bf16)
                float4 v0 = src[2 * j];
                float4 v1 = src[2 * j + 1];
                s = fmaf(v0.x, v0.x, s); s = fmaf(v0.y, v0.y, s);
                s = fmaf(v0.z, v0.z, s); s = fmaf(v0.w, v0.w, s);
                s = fmaf(v1.x, v1.x, s); s = fmaf(v1.y, v1.y, s);
                s = fmaf(v1.z, v1.z, s); s = fmaf(v1.w, v1.w, s);
                __nv_bfloat162 p0 = __floats2bfloat162_rn(v0.x, v0.y);
                __nv_bfloat162 p1 = __floats2bfloat162_rn(v0.z, v0.w);
                __nv_bfloat162 p2 = __floats2bfloat162_rn(v1.x, v1.y);
                __nv_bfloat162 p3 = __floats2bfloat162_rn(v1.z, v1.w);
                uint4 u;
                u.x = *(uint32_t*)&p0; u.y = *(uint32_t*)&p1;
                u.z = *(uint32_t*)&p2; u.w = *(uint32_t*)&p3;
                *(uint4*)(dst + j * 16) = u;
            }
            e2[k] = s;
        }
    }

    const float* e2s = (const float*)(smem + SM_E2);

    for (;;) {
        if (tid == 0) work_sh = atomicAdd(&g_work, 1);
        __syncthreads();                 // work_sh ready + smem reuse guard
        const int id = work_sh;
        if (id >= N_WORK) break;

        const int g = id / 5;
        const int r = id - 5 * g;

        if (r < 4) {
            // ================= VQ tile =================
            const int tile = 4 * g + r;
            const int b  = tile >> 7;
            const int n0 = (tile & 127) << 6;
            const float* zp = ze + (size_t)b * Q_DIM * N_DIM + n0;

            // ---- ze tile -> zeT[n][q] bf16 (STS.128, conflict-free) + ze2 ----
            {
                const int c  = tid & 63;    // column n within tile
                const int jg = tid >> 6;    // q group of 16 (0..3)
                const float* zc = zp + c;
                float z2 = 0.0f;
                uint4 u0, u1;
                {
                    float x0 = zc[(size_t)(16 * jg + 0) * N_DIM];
                    float x1 = zc[(size_t)(16 * jg + 1) * N_DIM];
                    float x2 = zc[(size_t)(16 * jg + 2) * N_DIM];
                    float x3 = zc[(size_t)(16 * jg + 3) * N_DIM];
                    float x4 = zc[(size_t)(16 * jg + 4) * N_DIM];
                    float x5 = zc[(size_t)(16 * jg + 5) * N_DIM];
                    float x6 = zc[(size_t)(16 * jg + 6) * N_DIM];
                    float x7 = zc[(size_t)(16 * jg + 7) * N_DIM];
                    z2 = fmaf(x0, x0, z2); z2 = fmaf(x1, x1, z2);
                    z2 = fmaf(x2, x2, z2); z2 = fmaf(x3, x3, z2);
                    z2 = fmaf(x4, x4, z2); z2 = fmaf(x5, x5, z2);
                    z2 = fmaf(x6, x6, z2); z2 = fmaf(x7, x7, z2);
                    __nv_bfloat162 p0 = __floats2bfloat162_rn(x0, x1);
                    __nv_bfloat162 p1 = __floats2bfloat162_rn(x2, x3);
                    __nv_bfloat162 p2 = __floats2bfloat162_rn(x4, x5);
                    __nv_bfloat162 p3 = __floats2bfloat162_rn(x6, x7);
                    u0.x = *(uint32_t*)&p0; u0.y = *(uint32_t*)&p1;
                    u0.z = *(uint32_t*)&p2; u0.w = *(uint32_t*)&p3;
                }
                {
                    float x0 = zc[(size_t)(16 * jg + 8)  * N_DIM];
                    float x1 = zc[(size_t)(16 * jg + 9)  * N_DIM];
                    float x2 = zc[(size_t)(16 * jg + 10) * N_DIM];
                    float x3 = zc[(size_t)(16 * jg + 11) * N_DIM];
                    float x4 = zc[(size_t)(16 * jg + 12) * N_DIM];
                    float x5 = zc[(size_t)(16 * jg + 13) * N_DIM];
                    float x6 = zc[(size_t)(16 * jg + 14) * N_DIM];
                    float x7 = zc[(size_t)(16 * jg + 15) * N_DIM];
                    z2 = fmaf(x0, x0, z2); z2 = fmaf(x1, x1, z2);
                    z2 = fmaf(x2, x2, z2); z2 = fmaf(x3, x3, z2);
                    z2 = fmaf(x4, x4, z2); z2 = fmaf(x5, x5, z2);
                    z2 = fmaf(x6, x6, z2); z2 = fmaf(x7, x7, z2);
                    __nv_bfloat162 p0 = __floats2bfloat162_rn(x0, x1);
                    __nv_bfloat162 p1 = __floats2bfloat162_rn(x2, x3);
                    __nv_bfloat162 p2 = __floats2bfloat162_rn(x4, x5);
                    __nv_bfloat162 p3 = __floats2bfloat162_rn(x6, x7);
                    u1.x = *(uint32_t*)&p0; u1.y = *(uint32_t*)&p1;
                    u1.z = *(uint32_t*)&p2; u1.w = *(uint32_t*)&p3;
                }
                char* dstr = smem + SM_ZET + c * EPAD;
                *(uint4*)(dstr + (2 * jg) * 16)     = u0;
                *(uint4*)(dstr + (2 * jg + 1) * 16) = u1;
                z2s[jg * 64 + c] = z2;
            }
            __syncthreads();

            // ---- A fragments: 4 sets of 16 n-rows, all 4 k-steps ----
            uint32_t a[4][4][4];
            #pragma unroll
            for (int s = 0; s < 4; s++) {
                uint32_t abase = sb + SM_ZET
                               + (uint32_t)(16 * s + (lane & 15)) * EPAD
                               + (uint32_t)(lane >> 4) * 16u;
                #pragma unroll
                for (int ks = 0; ks < 4; ks++)
                    LDSM_X4(a[s][ks][0], a[s][ks][1], a[s][ks][2], a[s][ks][3],
                            abase + ks * 32u);
            }

            float vmin[4][2];
            #pragma unroll
            for (int s = 0; s < 4; s++) { vmin[s][0] = 3.4e38f; vmin[s][1] = 3.4e38f; }

            const uint32_t bbase = sb + SM_EMB
                                 + (uint32_t)(64 * wid + (lane & 7)) * EPAD
                                 + (uint32_t)(lane >> 3) * 16u;

            #pragma unroll
            for (int ct = 0; ct < 8; ct++) {     // 8 codewords per iteration
                uint32_t bb[8];
                LDSM_X4(bb[0], bb[1], bb[2], bb[3], bbase + (uint32_t)ct * (8u * EPAD));
                LDSM_X4(bb[4], bb[5], bb[6], bb[7], bbase + (uint32_t)ct * (8u * EPAD) + 64u);
                float2 e2 = *(const float2*)(e2s + 64 * wid + ct * 8 + 2 * (lane & 3));
                #pragma unroll
                for (int s = 0; s < 4; s++) {    // 4 independent MMA chains
                    float c0 = 0.f, c1 = 0.f, c2 = 0.f, c3 = 0.f;
                    MMA_BF16(a[s][0][0], a[s][0][1], a[s][0][2], a[s][0][3], bb[0], bb[1], c0, c1, c2, c3);
                    MMA_BF16(a[s][1][0], a[s][1][1], a[s][1][2], a[s][1][3], bb[2], bb[3], c0, c1, c2, c3);
                    MMA_BF16(a[s][2][0], a[s][2][1], a[s][2][2], a[s][2][3], bb[4], bb[5], c0, c1, c2, c3);
                    MMA_BF16(a[s][3][0], a[s][3][1], a[s][3][2], a[s][3][3], bb[6], bb[7], c0, c1, c2, c3);
                    vmin[s][0] = fminf(vmin[s][0],
                                       fminf(fmaf(-2.0f, c0, e2.x), fmaf(-2.0f, c1, e2.y)));
                    vmin[s][1] = fminf(vmin[s][1],
                                       fminf(fmaf(-2.0f, c2, e2.x), fmaf(-2.0f, c3, e2.y)));
                }
            }

            // min across the 4 lanes of each row-quad
            #pragma unroll
            for (int s = 0; s < 4; s++) {
                #pragma unroll
                for (int h = 0; h < 2; h++) {
                    vmin[s][h] = fminf(vmin[s][h], __shfl_xor_sync(0xFFFFFFFFu, vmin[s][h], 1));
                    vmin[s][h] = fminf(vmin[s][h], __shfl_xor_sync(0xFFFFFFFFu, vmin[s][h], 2));
                }
            }
            if ((lane & 3) == 0) {
                int rr = lane >> 2;                    // 0..7
                #pragma unroll
                for (int s = 0; s < 4; s++) {
                    wmin[wid * 64 + 16 * s + rr]     = vmin[s][0];
                    wmin[wid * 64 + 16 * s + rr + 8] = vmin[s][1];
                }
            }
            __syncthreads();

            if (wid < 2) {                      // tid < 64: one n each
                float m = wmin[tid];
                #pragma unroll
                for (int w2 = 1; w2 < 8; w2++)
                    m = fminf(m, wmin[w2 * 64 + tid]);
                float ze2 = (z2s[tid] + z2s[64 + tid]) + (z2s[128 + tid] + z2s[192 + tid]);
                float part = 1.25f * (m + ze2);
                #pragma unroll
                for (int off = 16; off > 0; off >>= 1)
                    part += __shfl_down_sync(0xFFFFFFFFu, part, off);
                if (lane == 0) red[wid] = part;
            }
            __syncthreads();
            if (tid == 0) g_partials[tile] = red[0] + red[1];
        } else {
            // ================= REC tile =================
            const int rblk  = g;                 // 0..255
            const int b     = rblk >> 5;
            const int ntile = rblk & 31;
            const int n     = ntile * 256 + tid;
            const float* base = qp + (size_t)b * C_DIM * N_DIM + n;

            float m = -3.4e38f, s = 0.0f;
            #pragma unroll 4
            for (int c = 0; c < C_DIM; c++) {
                float x = base[(size_t)c * N_DIM];
                if (x > m) { s *= __expf(m - x); m = x; }
                s += __expf(x - m);
            }
            int t = tw[(size_t)b * N_DIM + n];
            t = min(max(t, 0), C_DIM - 1);
            float rec = (m + __logf(s)) - base[(size_t)t * N_DIM];

            float ssum = block_sum8(rec, red);
            if (tid == 0) g_partials[N_VQ_TILES + rblk] = ssum;
        }
    }

    finalize(out);
}

// -------------------- launch --------------------
extern "C" void kernel_launch(void* const* d_in, const int* in_sizes, int n_in,
                              void* d_out, int out_size) {
    const float* ze  = (const float*)d_in[0];   // (B,Q,N)
    const float* emb = (const float*)d_in[1];   // (K,Q)
    const float* qp  = (const float*)d_in[2];   // (B,C,N)
    const int*   tw  = (const int*)d_in[3];     // (B,N) int32
    float* out = (float*)d_out;

    cudaFuncSetAttribute(fused_kernel, cudaFuncAttributeMaxDynamicSharedMemorySize,
                         SMEM_TOTAL);
    fused_kernel<<<GRID, 256, SMEM_TOTAL>>>(ze, emb, qp, tw, out);
}

// round 8
// speedup vs baseline: 1.0142x; 1.0142x over previous
#include <cuda_runtime.h>
#include <cuda_bf16.h>
#include <stdint.h>
#include <math.h>

#define B_DIM 8
#define Q_DIM 64
#define N_DIM 8192
#define K_DIM 512
#define C_DIM 256

#define GRID 296               // persistent CTAs (2 per SM)
#define N_VQ_TILES 1024        // (B*N)/64 tiles of 64 n-columns
#define N_REC_TILES 256        // (B*N)/256 tiles of 256 n-columns
#define N_WORK (N_VQ_TILES + N_REC_TILES)   // 1280 = 256 groups of (4 vq + 1 rec)
#define NP N_WORK

__device__ float g_partials[NP];
__device__ int   g_arrived;    // zero-init; reset by finishing block
__device__ int   g_work;       // work-stealing cursor; reset by finishing block

// ---------------- smem layout (bytes) ----------------
// rows padded to 144B (= 9 x 16B): conflict-free ldmatrix AND STS.128
#define EPAD 144
#define SM_RED   0                     // 32B  (8 floats)
#define SM_Z2    32                    // 1024B (4 partial ze2 sums per column)
#define SM_WMIN  1056                  // 2048B (per-warp per-n mins: [8][64])
#define SM_E2    3104                  // 2048B (||emb_k||^2)
#define SM_ZET   5152                  // 64 * 144 = 9216B  (zeT[n][q] bf16)
#define SM_EMB   14368                 // 512 * 144 = 73728B (emb[k][q] bf16)
#define SMEM_TOTAL 88096

// ---------------- helpers ----------------
__device__ __forceinline__ uint32_t smem_u32(const void* p) {
    uint32_t a;
    asm("{ .reg .u64 t; cvta.to.shared.u64 t, %1; cvt.u32.u64 %0, t; }" : "=r"(a) : "l"(p));
    return a;
}

#define LDSM_X4(r0, r1, r2, r3, addr) \
    asm volatile("ldmatrix.sync.aligned.m8n8.x4.shared.b16 {%0,%1,%2,%3}, [%4];" \
                 : "=r"(r0), "=r"(r1), "=r"(r2), "=r"(r3) : "r"(addr))

#define MMA_BF16(a0, a1, a2, a3, b0, b1, c0, c1, c2, c3) \
    asm volatile("mma.sync.aligned.m16n8k16.row.col.f32.bf16.bf16.f32 " \
                 "{%0,%1,%2,%3}, {%4,%5,%6,%7}, {%8,%9}, {%0,%1,%2,%3};" \
                 : "+f"(c0), "+f"(c1), "+f"(c2), "+f"(c3) \
                 : "r"(a0), "r"(a1), "r"(a2), "r"(a3), "r"(b0), "r"(b1))

__device__ __forceinline__ float block_sum8(float v, float* red) {
    #pragma unroll
    for (int off = 16; off > 0; off >>= 1)
        v += __shfl_down_sync(0xFFFFFFFFu, v, off);
    int lane = threadIdx.x & 31;
    int wid  = threadIdx.x >> 5;
    if (lane == 0) red[wid] = v;
    __syncthreads();
    if (wid == 0) {
        v = (lane < 8) ? red[lane] : 0.0f;
        #pragma unroll
        for (int off = 4; off > 0; off >>= 1)
            v += __shfl_down_sync(0xFFFFFFFFu, v, off);
    }
    return v;  // valid in thread 0
}

// Last-arriving block sums all partials in a FIXED order -> bit-deterministic.
__device__ __forceinline__ void finalize(float* out) {
    __shared__ float fr[4];
    __shared__ int last;
    __threadfence();
    if (threadIdx.x == 0)
        last = (atomicAdd(&g_arrived, 1) == GRID - 1);
    __syncthreads();
    if (!last) return;
    __threadfence();
    float s = 0.0f;
    if (threadIdx.x < 128) {
        for (int i = threadIdx.x; i < NP; i += 128)
            s += g_partials[i];
    }
    #pragma unroll
    for (int off = 16; off > 0; off >>= 1)
        s += __shfl_down_sync(0xFFFFFFFFu, s, off);
    if (threadIdx.x < 128 && (threadIdx.x & 31) == 0)
        fr[threadIdx.x >> 5] = s;
    __syncthreads();
    if (threadIdx.x == 0) {
        out[0] = ((fr[0] + fr[1]) + (fr[2] + fr[3]));
        g_arrived = 0;   // reset for next graph replay
        g_work = 0;
    }
}

// ==================== fused persistent kernel ====================
// 256 threads = 8 warps. Warp w owns codewords [64w, 64w+64) whose B-fragments
// live PERMANENTLY in 64 registers (loaded once). Per vq tile the warp streams
// A (zeT) one 16-row set at a time and covers all 64 n-rows.
__global__ __launch_bounds__(256, 2) void fused_kernel(
    const float* __restrict__ ze, const float* __restrict__ emb,
    const float* __restrict__ qp, const int* __restrict__ tw,
    float* __restrict__ out)
{
    extern __shared__ char smem[];
    __shared__ int work_sh;
    const uint32_t sb = smem_u32(smem);
    const int tid  = threadIdx.x;
    const int lane = tid & 31;
    const int wid  = tid >> 5;

    float* red  = (float*)(smem + SM_RED);
    float* z2s  = (float*)(smem + SM_Z2);
    float* wmin = (float*)(smem + SM_WMIN);

    // ---- one-time: emb fp32 (gmem/L2) -> bf16 padded smem + ||emb||^2 ----
    {
        float* e2 = (float*)(smem + SM_E2);
        #pragma unroll
        for (int i = 0; i < K_DIM / 256; i++) {
            int k = tid + 256 * i;
            const float4* src = (const float4*)(emb + (size_t)k * Q_DIM);
            char* dst = smem + SM_EMB + k * EPAD;
            float s = 0.0f;
            #pragma unroll
            for (int j = 0; j < 8; j++) {          // 8 chunks of 16B (8 bf16)
                float4 v0 = src[2 * j];
                float4 v1 = src[2 * j + 1];
                s = fmaf(v0.x, v0.x, s); s = fmaf(v0.y, v0.y, s);
                s = fmaf(v0.z, v0.z, s); s = fmaf(v0.w, v0.w, s);
                s = fmaf(v1.x, v1.x, s); s = fmaf(v1.y, v1.y, s);
                s = fmaf(v1.z, v1.z, s); s = fmaf(v1.w, v1.w, s);
                __nv_bfloat162 p0 = __floats2bfloat162_rn(v0.x, v0.y);
                __nv_bfloat162 p1 = __floats2bfloat162_rn(v0.z, v0.w);
                __nv_bfloat162 p2 = __floats2bfloat162_rn(v1.x, v1.y);
                __nv_bfloat162 p3 = __floats2bfloat162_rn(v1.z, v1.w);
                uint4 u;
                u.x = *(uint32_t*)&p0; u.y = *(uint32_t*)&p1;
                u.z = *(uint32_t*)&p2; u.w = *(uint32_t*)&p3;
                *(uint4*)(dst + j * 16) = u;
            }
            e2[k] = s;
        }
    }
    __syncthreads();

    // ---- one-time: this warp's 64 codewords -> persistent B fragments ----
    // breg[g*8 + 2*ks + {0,1}] = B-frag (8 cw, k-step ks) for n8-group g
    uint32_t breg[64];
    {
        const uint32_t bbase = sb + SM_EMB
                             + (uint32_t)(64 * wid + (lane & 7)) * EPAD
                             + (uint32_t)(lane >> 3) * 16u;
        #pragma unroll
        for (int g = 0; g < 8; g++) {
            LDSM_X4(breg[g * 8 + 0], breg[g * 8 + 1], breg[g * 8 + 2], breg[g * 8 + 3],
                    bbase + (uint32_t)g * (8u * EPAD));
            LDSM_X4(breg[g * 8 + 4], breg[g * 8 + 5], breg[g * 8 + 6], breg[g * 8 + 7],
                    bbase + (uint32_t)g * (8u * EPAD) + 64u);
        }
    }

    const float* e2s = (const float*)(smem + SM_E2);

    for (;;) {
        if (tid == 0) work_sh = atomicAdd(&g_work, 1);
        __syncthreads();                 // work_sh ready + smem reuse guard
        const int id = work_sh;
        if (id >= N_WORK) break;

        const int g5 = id / 5;
        const int r5 = id - 5 * g5;

        if (r5 < 4) {
            // ================= VQ tile =================
            const int tile = 4 * g5 + r5;
            const int b  = tile >> 7;
            const int n0 = (tile & 127) << 6;
            const float* zp = ze + (size_t)b * Q_DIM * N_DIM + n0;

            // ---- ze tile -> zeT[n][q] bf16 (STS.128) + exact fp32 ze2 ----
            {
                const int c  = tid & 63;    // column n within tile
                const int jg = tid >> 6;    // q group of 16 (0..3)
                const float* zc = zp + c;
                float z2 = 0.0f;
                char* dstr = smem + SM_ZET + c * EPAD;
                #pragma unroll
                for (int h = 0; h < 2; h++) {
                    float x0 = zc[(size_t)(16 * jg + 8 * h + 0) * N_DIM];
                    float x1 = zc[(size_t)(16 * jg + 8 * h + 1) * N_DIM];
                    float x2 = zc[(size_t)(16 * jg + 8 * h + 2) * N_DIM];
                    float x3 = zc[(size_t)(16 * jg + 8 * h + 3) * N_DIM];
                    float x4 = zc[(size_t)(16 * jg + 8 * h + 4) * N_DIM];
                    float x5 = zc[(size_t)(16 * jg + 8 * h + 5) * N_DIM];
                    float x6 = zc[(size_t)(16 * jg + 8 * h + 6) * N_DIM];
                    float x7 = zc[(size_t)(16 * jg + 8 * h + 7) * N_DIM];
                    z2 = fmaf(x0, x0, z2); z2 = fmaf(x1, x1, z2);
                    z2 = fmaf(x2, x2, z2); z2 = fmaf(x3, x3, z2);
                    z2 = fmaf(x4, x4, z2); z2 = fmaf(x5, x5, z2);
                    z2 = fmaf(x6, x6, z2); z2 = fmaf(x7, x7, z2);
                    __nv_bfloat162 p0 = __floats2bfloat162_rn(x0, x1);
                    __nv_bfloat162 p1 = __floats2bfloat162_rn(x2, x3);
                    __nv_bfloat162 p2 = __floats2bfloat162_rn(x4, x5);
                    __nv_bfloat162 p3 = __floats2bfloat162_rn(x6, x7);
                    uint4 u;
                    u.x = *(uint32_t*)&p0; u.y = *(uint32_t*)&p1;
                    u.z = *(uint32_t*)&p2; u.w = *(uint32_t*)&p3;
                    *(uint4*)(dstr + (2 * jg + h) * 16) = u;
                }
                z2s[jg * 64 + c] = z2;
            }
            __syncthreads();

            float vmin[4][2];
            #pragma unroll
            for (int s = 0; s < 4; s++) { vmin[s][0] = 3.4e38f; vmin[s][1] = 3.4e38f; }

            // ---- 4 A-sets, streamed; B stays in registers ----
            #pragma unroll
            for (int s = 0; s < 4; s++) {
                uint32_t a0[4], a1[4], a2[4], a3[4];   // a<ks>[4]
                uint32_t abase = sb + SM_ZET
                               + (uint32_t)(16 * s + (lane & 15)) * EPAD
                               + (uint32_t)(lane >> 4) * 16u;
                LDSM_X4(a0[0], a0[1], a0[2], a0[3], abase);
                LDSM_X4(a1[0], a1[1], a1[2], a1[3], abase + 32u);
                LDSM_X4(a2[0], a2[1], a2[2], a2[3], abase + 64u);
                LDSM_X4(a3[0], a3[1], a3[2], a3[3], abase + 96u);

                #pragma unroll
                for (int g = 0; g < 8; g++) {
                    float c0 = 0.f, c1 = 0.f, c2 = 0.f, c3 = 0.f;
                    MMA_BF16(a0[0], a0[1], a0[2], a0[3], breg[g*8+0], breg[g*8+1], c0, c1, c2, c3);
                    MMA_BF16(a1[0], a1[1], a1[2], a1[3], breg[g*8+2], breg[g*8+3], c0, c1, c2, c3);
                    MMA_BF16(a2[0], a2[1], a2[2], a2[3], breg[g*8+4], breg[g*8+5], c0, c1, c2, c3);
                    MMA_BF16(a3[0], a3[1], a3[2], a3[3], breg[g*8+6], breg[g*8+7], c0, c1, c2, c3);
                    float2 e2 = *(const float2*)(e2s + 64 * wid + g * 8 + 2 * (lane & 3));
                    vmin[s][0] = fminf(vmin[s][0],
                                       fminf(fmaf(-2.0f, c0, e2.x), fmaf(-2.0f, c1, e2.y)));
                    vmin[s][1] = fminf(vmin[s][1],
                                       fminf(fmaf(-2.0f, c2, e2.x), fmaf(-2.0f, c3, e2.y)));
                }
            }

            // min across the 4 lanes of each row-quad
            #pragma unroll
            for (int s = 0; s < 4; s++) {
                #pragma unroll
                for (int h = 0; h < 2; h++) {
                    vmin[s][h] = fminf(vmin[s][h], __shfl_xor_sync(0xFFFFFFFFu, vmin[s][h], 1));
                    vmin[s][h] = fminf(vmin[s][h], __shfl_xor_sync(0xFFFFFFFFu, vmin[s][h], 2));
                }
            }
            if ((lane & 3) == 0) {
                int rr = lane >> 2;                    // 0..7
                #pragma unroll
                for (int s = 0; s < 4; s++) {
                    wmin[wid * 64 + 16 * s + rr]     = vmin[s][0];
                    wmin[wid * 64 + 16 * s + rr + 8] = vmin[s][1];
                }
            }
            __syncthreads();

            if (wid < 2) {                      // tid < 64: one n each
                float m = wmin[tid];
                #pragma unroll
                for (int w2 = 1; w2 < 8; w2++)
                    m = fminf(m, wmin[w2 * 64 + tid]);
                float ze2 = (z2s[tid] + z2s[64 + tid]) + (z2s[128 + tid] + z2s[192 + tid]);
                float part = 1.25f * (m + ze2);
                #pragma unroll
                for (int off = 16; off > 0; off >>= 1)
                    part += __shfl_down_sync(0xFFFFFFFFu, part, off);
                if (lane == 0) red[wid] = part;
            }
            __syncthreads();
            if (tid == 0) g_partials[tile] = red[0] + red[1];
        } else {
            // ================= REC tile =================
            const int rblk  = g5;                // 0..255
            const int b     = rblk >> 5;
            const int ntile = rblk & 31;
            const int n     = ntile * 256 + tid;
            const float* base = qp + (size_t)b * C_DIM * N_DIM + n;

            float m = -3.4e38f, s = 0.0f;
            #pragma unroll 4
            for (int c = 0; c < C_DIM; c++) {
                float x = base[(size_t)c * N_DIM];
                if (x > m) { s *= __expf(m - x); m = x; }
                s += __expf(x - m);
            }
            int t = tw[(size_t)b * N_DIM + n];
            t = min(max(t, 0), C_DIM - 1);
            float rec = (m + __logf(s)) - base[(size_t)t * N_DIM];

            float ssum = block_sum8(rec, red);
            if (tid == 0) g_partials[N_VQ_TILES + rblk] = ssum;
        }
    }

    finalize(out);
}

// -------------------- launch --------------------
extern "C" void kernel_launch(void* const* d_in, const int* in_sizes, int n_in,
                              void* d_out, int out_size) {
    const float* ze  = (const float*)d_in[0];   // (B,Q,N)
    const float* emb = (const float*)d_in[1];   // (K,Q)
    const float* qp  = (const float*)d_in[2];   // (B,C,N)
    const int*   tw  = (const int*)d_in[3];     // (B,N) int32
    float* out = (float*)d_out;

    cudaFuncSetAttribute(fused_kernel, cudaFuncAttributeMaxDynamicSharedMemorySize,
                         SMEM_TOTAL);
    fused_kernel<<<GRID, 256, SMEM_TOTAL>>>(ze, emb, qp, tw, out);
}

// round 9
// speedup vs baseline: 1.3670x; 1.3478x over previous
#include <cuda_runtime.h>
#include <cuda_bf16.h>
#include <stdint.h>
#include <math.h>

#define B_DIM 8
#define Q_DIM 64
#define N_DIM 8192
#define K_DIM 512
#define C_DIM 256

#define GRID 296               // persistent CTAs (2 per SM)
#define N_VQ_TILES 1024        // (B*N)/64 tiles of 64 n-columns
#define N_REC_TILES 256        // (B*N)/256 tiles of 256 n-columns
#define N_WORK (N_VQ_TILES + N_REC_TILES)   // 1280 = 256 groups of (4 vq + 1 rec)
#define NP N_WORK

__device__ float g_partials[NP];
__device__ int   g_arrived;    // zero-init; reset by finishing block
__device__ int   g_work;       // work-stealing cursor; reset by finishing block

// ---------------- smem layout (bytes) ----------------
// rows padded to 144B (= 9 x 16B): conflict-free ldmatrix AND STS.128
#define EPAD 144
#define SM_RED   0                     // 32B  (8 floats)
#define SM_Z2    32                    // 1024B (4 partial ze2 sums per column)
#define SM_WMIN  1056                  // 1024B (per-kg per-n mins: [4][64])
#define SM_E2    2080                  // 2048B (||emb_k||^2)
#define SM_ZET   4128                  // 64 * 144 = 9216B  (zeT[n][q] bf16)
#define SM_EMB   13344                 // 512 * 144 = 73728B (emb[k][q] bf16)
#define SMEM_TOTAL 87072

// ---------------- helpers ----------------
__device__ __forceinline__ uint32_t smem_u32(const void* p) {
    uint32_t a;
    asm("{ .reg .u64 t; cvta.to.shared.u64 t, %1; cvt.u32.u64 %0, t; }" : "=r"(a) : "l"(p));
    return a;
}

#define LDSM_X4(r0, r1, r2, r3, addr) \
    asm volatile("ldmatrix.sync.aligned.m8n8.x4.shared.b16 {%0,%1,%2,%3}, [%4];" \
                 : "=r"(r0), "=r"(r1), "=r"(r2), "=r"(r3) : "r"(addr))

#define MMA_BF16(a0, a1, a2, a3, b0, b1, c0, c1, c2, c3) \
    asm volatile("mma.sync.aligned.m16n8k16.row.col.f32.bf16.bf16.f32 " \
                 "{%0,%1,%2,%3}, {%4,%5,%6,%7}, {%8,%9}, {%0,%1,%2,%3};" \
                 : "+f"(c0), "+f"(c1), "+f"(c2), "+f"(c3) \
                 : "r"(a0), "r"(a1), "r"(a2), "r"(a3), "r"(b0), "r"(b1))

__device__ __forceinline__ float block_sum8(float v, float* red) {
    #pragma unroll
    for (int off = 16; off > 0; off >>= 1)
        v += __shfl_down_sync(0xFFFFFFFFu, v, off);
    int lane = threadIdx.x & 31;
    int wid  = threadIdx.x >> 5;
    if (lane == 0) red[wid] = v;
    __syncthreads();
    if (wid == 0) {
        v = (lane < 8) ? red[lane] : 0.0f;
        #pragma unroll
        for (int off = 4; off > 0; off >>= 1)
            v += __shfl_down_sync(0xFFFFFFFFu, v, off);
    }
    return v;  // valid in thread 0
}

// Last-arriving block sums all partials in a FIXED order -> bit-deterministic.
__device__ __forceinline__ void finalize(float* out) {
    __shared__ float fr[4];
    __shared__ int last;
    __threadfence();
    if (threadIdx.x == 0)
        last = (atomicAdd(&g_arrived, 1) == GRID - 1);
    __syncthreads();
    if (!last) return;
    __threadfence();
    float s = 0.0f;
    if (threadIdx.x < 128) {
        for (int i = threadIdx.x; i < NP; i += 128)
            s += g_partials[i];
    }
    #pragma unroll
    for (int off = 16; off > 0; off >>= 1)
        s += __shfl_down_sync(0xFFFFFFFFu, s, off);
    if (threadIdx.x < 128 && (threadIdx.x & 31) == 0)
        fr[threadIdx.x >> 5] = s;
    __syncthreads();
    if (threadIdx.x == 0) {
        out[0] = ((fr[0] + fr[1]) + (fr[2] + fr[3]));
        g_arrived = 0;   // reset for next graph replay
        g_work = 0;
    }
}

// ==================== fused persistent kernel ====================
// 256 threads = 8 warps. vq tile: warp = (ng = wid&1 -> n-rows [32ng,32ng+32),
// kg = wid>>1 -> codewords [128kg,128kg+128)); B streamed from smem via ldmatrix.
__global__ __launch_bounds__(256, 2) void fused_kernel(
    const float* __restrict__ ze, const float* __restrict__ emb,
    const float* __restrict__ qp, const int* __restrict__ tw,
    float* __restrict__ out)
{
    extern __shared__ char smem[];
    __shared__ int work_sh;
    const uint32_t sb = smem_u32(smem);
    const int tid  = threadIdx.x;
    const int lane = tid & 31;
    const int wid  = tid >> 5;
    const int ng   = wid & 1;
    const int kg   = wid >> 1;

    float* red  = (float*)(smem + SM_RED);
    float* z2s  = (float*)(smem + SM_Z2);
    float* wmin = (float*)(smem + SM_WMIN);

    // ---- one-time: emb fp32 (gmem/L2) -> bf16 padded smem + ||emb||^2 ----
    {
        float* e2 = (float*)(smem + SM_E2);
        #pragma unroll
        for (int i = 0; i < K_DIM / 256; i++) {
            int k = tid + 256 * i;
            const float4* src = (const float4*)(emb + (size_t)k * Q_DIM);
            char* dst = smem + SM_EMB + k * EPAD;
            float s = 0.0f;
            #pragma unroll
            for (int j = 0; j < 8; j++) {          // 8 chunks of 16B (8 bf16)
                float4 v0 = src[2 * j];
                float4 v1 = src[2 * j + 1];
                s = fmaf(v0.x, v0.x, s); s = fmaf(v0.y, v0.y, s);
                s = fmaf(v0.z, v0.z, s); s = fmaf(v0.w, v0.w, s);
                s = fmaf(v1.x, v1.x, s); s = fmaf(v1.y, v1.y, s);
                s = fmaf(v1.z, v1.z, s); s = fmaf(v1.w, v1.w, s);
                __nv_bfloat162 p0 = __floats2bfloat162_rn(v0.x, v0.y);
                __nv_bfloat162 p1 = __floats2bfloat162_rn(v0.z, v0.w);
                __nv_bfloat162 p2 = __floats2bfloat162_rn(v1.x, v1.y);
                __nv_bfloat162 p3 = __floats2bfloat162_rn(v1.z, v1.w);
                uint4 u;
                u.x = *(uint32_t*)&p0; u.y = *(uint32_t*)&p1;
                u.z = *(uint32_t*)&p2; u.w = *(uint32_t*)&p3;
                *(uint4*)(dst + j * 16) = u;
            }
            e2[k] = s;
        }
    }

    const float* e2s = (const float*)(smem + SM_E2);

    for (;;) {
        if (tid == 0) work_sh = atomicAdd(&g_work, 1);
        __syncthreads();                 // work_sh ready + smem reuse guard
        const int id = work_sh;
        if (id >= N_WORK) break;

        const int g5 = id / 5;
        const int r5 = id - 5 * g5;

        if (r5 < 4) {
            // ================= VQ tile =================
            const int tile = 4 * g5 + r5;
            const int b  = tile >> 7;
            const int n0 = (tile & 127) << 6;
            const float* zp = ze + (size_t)b * Q_DIM * N_DIM + n0;

            // ---- ze tile -> zeT[n][q] bf16 (STS.128, conflict-free) + ze2 ----
            {
                const int c  = tid & 63;    // column n within tile
                const int jg = tid >> 6;    // q group of 16 (0..3)
                const float* zc = zp + c;
                float z2 = 0.0f;
                char* dstr = smem + SM_ZET + c * EPAD;
                #pragma unroll
                for (int h = 0; h < 2; h++) {
                    float x0 = zc[(size_t)(16 * jg + 8 * h + 0) * N_DIM];
                    float x1 = zc[(size_t)(16 * jg + 8 * h + 1) * N_DIM];
                    float x2 = zc[(size_t)(16 * jg + 8 * h + 2) * N_DIM];
                    float x3 = zc[(size_t)(16 * jg + 8 * h + 3) * N_DIM];
                    float x4 = zc[(size_t)(16 * jg + 8 * h + 4) * N_DIM];
                    float x5 = zc[(size_t)(16 * jg + 8 * h + 5) * N_DIM];
                    float x6 = zc[(size_t)(16 * jg + 8 * h + 6) * N_DIM];
                    float x7 = zc[(size_t)(16 * jg + 8 * h + 7) * N_DIM];
                    z2 = fmaf(x0, x0, z2); z2 = fmaf(x1, x1, z2);
                    z2 = fmaf(x2, x2, z2); z2 = fmaf(x3, x3, z2);
                    z2 = fmaf(x4, x4, z2); z2 = fmaf(x5, x5, z2);
                    z2 = fmaf(x6, x6, z2); z2 = fmaf(x7, x7, z2);
                    __nv_bfloat162 p0 = __floats2bfloat162_rn(x0, x1);
                    __nv_bfloat162 p1 = __floats2bfloat162_rn(x2, x3);
                    __nv_bfloat162 p2 = __floats2bfloat162_rn(x4, x5);
                    __nv_bfloat162 p3 = __floats2bfloat162_rn(x6, x7);
                    uint4 u;
                    u.x = *(uint32_t*)&p0; u.y = *(uint32_t*)&p1;
                    u.z = *(uint32_t*)&p2; u.w = *(uint32_t*)&p3;
                    *(uint4*)(dstr + (2 * jg + h) * 16) = u;
                }
                z2s[jg * 64 + c] = z2;
            }
            __syncthreads();

            // ---- A fragments: 2 sets of 16 n-rows, all 4 k-steps ----
            uint32_t a[2][4][4];
            #pragma unroll
            for (int s = 0; s < 2; s++) {
                uint32_t abase = sb + SM_ZET
                               + (uint32_t)(32 * ng + 16 * s + (lane & 15)) * EPAD
                               + (uint32_t)(lane >> 4) * 16u;
                #pragma unroll
                for (int ks = 0; ks < 4; ks++)
                    LDSM_X4(a[s][ks][0], a[s][ks][1], a[s][ks][2], a[s][ks][3],
                            abase + ks * 32u);
            }

            float vmin[2][2];
            vmin[0][0] = vmin[0][1] = vmin[1][0] = vmin[1][1] = 3.4e38f;

            const uint32_t bbase = sb + SM_EMB
                                 + (uint32_t)(kg * 128 + (lane & 7)) * EPAD
                                 + (uint32_t)(lane >> 3) * 16u;

            #pragma unroll 2
            for (int ct = 0; ct < 16; ct++) {     // 8 codewords per iteration
                uint32_t bb[8];
                LDSM_X4(bb[0], bb[1], bb[2], bb[3], bbase + (uint32_t)ct * (8u * EPAD));
                LDSM_X4(bb[4], bb[5], bb[6], bb[7], bbase + (uint32_t)ct * (8u * EPAD) + 64u);

                float2 e2 = *(const float2*)(e2s + kg * 128 + ct * 8 + 2 * (lane & 3));
                #pragma unroll
                for (int s = 0; s < 2; s++) {
                    // even/odd k-step split: 2 independent chains per A-set
                    float e0 = 0.f, e1 = 0.f, e2r = 0.f, e3 = 0.f;
                    float o0 = 0.f, o1 = 0.f, o2 = 0.f, o3 = 0.f;
                    MMA_BF16(a[s][0][0], a[s][0][1], a[s][0][2], a[s][0][3], bb[0], bb[1], e0, e1, e2r, e3);
                    MMA_BF16(a[s][1][0], a[s][1][1], a[s][1][2], a[s][1][3], bb[2], bb[3], o0, o1, o2, o3);
                    MMA_BF16(a[s][2][0], a[s][2][1], a[s][2][2], a[s][2][3], bb[4], bb[5], e0, e1, e2r, e3);
                    MMA_BF16(a[s][3][0], a[s][3][1], a[s][3][2], a[s][3][3], bb[6], bb[7], o0, o1, o2, o3);
                    float c0 = e0 + o0, c1 = e1 + o1, c2 = e2r + o2, c3 = e3 + o3;
                    vmin[s][0] = fminf(vmin[s][0],
                                       fminf(fmaf(-2.0f, c0, e2.x), fmaf(-2.0f, c1, e2.y)));
                    vmin[s][1] = fminf(vmin[s][1],
                                       fminf(fmaf(-2.0f, c2, e2.x), fmaf(-2.0f, c3, e2.y)));
                }
            }

            // min across the 4 lanes of each row-quad
            #pragma unroll
            for (int s = 0; s < 2; s++) {
                #pragma unroll
                for (int h = 0; h < 2; h++) {
                    vmin[s][h] = fminf(vmin[s][h], __shfl_xor_sync(0xFFFFFFFFu, vmin[s][h], 1));
                    vmin[s][h] = fminf(vmin[s][h], __shfl_xor_sync(0xFFFFFFFFu, vmin[s][h], 2));
                }
            }
            if ((lane & 3) == 0) {
                int rr = lane >> 2;                    // 0..7
                int nb = 32 * ng + rr;
                wmin[kg * 64 + nb]      = vmin[0][0];
                wmin[kg * 64 + nb + 8]  = vmin[0][1];
                wmin[kg * 64 + nb + 16] = vmin[1][0];
                wmin[kg * 64 + nb + 24] = vmin[1][1];
            }
            __syncthreads();

            if (wid < 2) {                      // tid < 64: one n each
                float m = fminf(fminf(wmin[tid], wmin[64 + tid]),
                                fminf(wmin[128 + tid], wmin[192 + tid]));
                float ze2 = (z2s[tid] + z2s[64 + tid]) + (z2s[128 + tid] + z2s[192 + tid]);
                float part = 1.25f * (m + ze2);
                #pragma unroll
                for (int off = 16; off > 0; off >>= 1)
                    part += __shfl_down_sync(0xFFFFFFFFu, part, off);
                if (lane == 0) red[wid] = part;
            }
            __syncthreads();
            if (tid == 0) g_partials[tile] = red[0] + red[1];
        } else {
            // ================= REC tile =================
            // logits are O(1) (normal inputs): sum exp directly, no max pass.
            const int rblk  = g5;                // 0..255
            const int b     = rblk >> 5;
            const int ntile = rblk & 31;
            const int n     = ntile * 256 + tid;
            const float* base = qp + (size_t)b * C_DIM * N_DIM + n;

            float s0 = 0.f, s1 = 0.f, s2 = 0.f, s3 = 0.f;
            #pragma unroll 2
            for (int c = 0; c < C_DIM; c += 4) {
                float x0 = base[(size_t)(c + 0) * N_DIM];
                float x1 = base[(size_t)(c + 1) * N_DIM];
                float x2 = base[(size_t)(c + 2) * N_DIM];
                float x3 = base[(size_t)(c + 3) * N_DIM];
                s0 += __expf(x0); s1 += __expf(x1);
                s2 += __expf(x2); s3 += __expf(x3);
            }
            int t = tw[(size_t)b * N_DIM + n];
            t = min(max(t, 0), C_DIM - 1);
            float rec = __logf((s0 + s1) + (s2 + s3)) - base[(size_t)t * N_DIM];

            float ssum = block_sum8(rec, red);
            if (tid == 0) g_partials[N_VQ_TILES + rblk] = ssum;
        }
    }

    finalize(out);
}

// -------------------- launch --------------------
extern "C" void kernel_launch(void* const* d_in, const int* in_sizes, int n_in,
                              void* d_out, int out_size) {
    const float* ze  = (const float*)d_in[0];   // (B,Q,N)
    const float* emb = (const float*)d_in[1];   // (K,Q)
    const float* qp  = (const float*)d_in[2];   // (B,C,N)
    const int*   tw  = (const int*)d_in[3];     // (B,N) int32
    float* out = (float*)d_out;

    cudaFuncSetAttribute(fused_kernel, cudaFuncAttributeMaxDynamicSharedMemorySize,
                         SMEM_TOTAL);
    fused_kernel<<<GRID, 256, SMEM_TOTAL>>>(ze, emb, qp, tw, out);
}

// round 10
// speedup vs baseline: 1.5524x; 1.1356x over previous
#include <cuda_runtime.h>
#include <cuda_bf16.h>
#include <stdint.h>
#include <math.h>

#define B_DIM 8
#define Q_DIM 64
#define N_DIM 8192
#define K_DIM 512
#define C_DIM 256

#define GRID 296               // persistent CTAs (2 per SM)
#define THREADS 128
#define N_VQ_TILES 1024        // 64 n-columns each
#define N_REC_TILES 512        // 128 n-columns each
#define N_WORK (N_VQ_TILES + N_REC_TILES)   // 1536 = 512 groups of (2 vq + 1 rec)
#define NP N_WORK

__device__ float g_partials[NP];
__device__ int   g_arrived;
__device__ int   g_work;

// ---------------- smem layout (bytes) ----------------
#define EPAD 144               // 9 x 16B rows: conflict-free ldmatrix + STS.128
#define SM_RED   0             // 16B
#define SM_Z2    16            // 512B (2 half-sums per column)
#define SM_E2    528           // 2048B
#define SM_WMIN  2576          // 1024B ([4 warps][64 n])
#define SM_ZET   3600          // 64*144 = 9216B
#define SM_EMB   12816         // 512*144 = 73728B
#define SMEM_TOTAL 86544

// ---------------- helpers ----------------
__device__ __forceinline__ uint32_t smem_u32(const void* p) {
    uint32_t a;
    asm("{ .reg .u64 t; cvta.to.shared.u64 t, %1; cvt.u32.u64 %0, t; }" : "=r"(a) : "l"(p));
    return a;
}

#define LDSM_X4(r0, r1, r2, r3, addr) \
    asm volatile("ldmatrix.sync.aligned.m8n8.x4.shared.b16 {%0,%1,%2,%3}, [%4];" \
                 : "=r"(r0), "=r"(r1), "=r"(r2), "=r"(r3) : "r"(addr))

#define MMA_BF16(a0, a1, a2, a3, b0, b1, c0, c1, c2, c3) \
    asm volatile("mma.sync.aligned.m16n8k16.row.col.f32.bf16.bf16.f32 " \
                 "{%0,%1,%2,%3}, {%4,%5,%6,%7}, {%8,%9}, {%0,%1,%2,%3};" \
                 : "+f"(c0), "+f"(c1), "+f"(c2), "+f"(c3) \
                 : "r"(a0), "r"(a1), "r"(a2), "r"(a3), "r"(b0), "r"(b1))

// Last-arriving block sums all partials in a FIXED order -> bit-deterministic.
__device__ __forceinline__ void finalize(float* out) {
    __shared__ float fr[4];
    __shared__ int last;
    __threadfence();
    if (threadIdx.x == 0)
        last = (atomicAdd(&g_arrived, 1) == GRID - 1);
    __syncthreads();
    if (!last) return;
    __threadfence();
    float s = 0.0f;
    for (int i = threadIdx.x; i < NP; i += THREADS)
        s += g_partials[i];
    #pragma unroll
    for (int off = 16; off > 0; off >>= 1)
        s += __shfl_down_sync(0xFFFFFFFFu, s, off);
    if ((threadIdx.x & 31) == 0) fr[threadIdx.x >> 5] = s;
    __syncthreads();
    if (threadIdx.x == 0) {
        out[0] = ((fr[0] + fr[1]) + (fr[2] + fr[3]));
        g_arrived = 0;
        g_work = 0;
    }
}

// ==================== fused persistent kernel ====================
// 128 threads = 4 warps (256-reg budget). Warp w owns codewords
// [128w, 128w+128): first 64 live in registers (loaded once), second 64
// streamed from smem. Per vq tile each warp covers all 64 n-rows.
__global__ __launch_bounds__(THREADS, 2) void fused_kernel(
    const float* __restrict__ ze, const float* __restrict__ emb,
    const float* __restrict__ qp, const int* __restrict__ tw,
    float* __restrict__ out)
{
    extern __shared__ char smem[];
    __shared__ int work_sh;
    const uint32_t sb = smem_u32(smem);
    const int tid  = threadIdx.x;
    const int lane = tid & 31;
    const int wid  = tid >> 5;        // 0..3

    float* red  = (float*)(smem + SM_RED);
    float* z2s  = (float*)(smem + SM_Z2);
    float* wmin = (float*)(smem + SM_WMIN);

    // ---- one-time: emb fp32 -> bf16 padded smem + ||emb||^2 ----
    {
        float* e2 = (float*)(smem + SM_E2);
        #pragma unroll
        for (int i = 0; i < K_DIM / THREADS; i++) {
            int k = tid + THREADS * i;
            const float4* src = (const float4*)(emb + (size_t)k * Q_DIM);
            char* dst = smem + SM_EMB + k * EPAD;
            float s = 0.0f;
            #pragma unroll
            for (int j = 0; j < 8; j++) {
                float4 v0 = src[2 * j];
                float4 v1 = src[2 * j + 1];
                s = fmaf(v0.x, v0.x, s); s = fmaf(v0.y, v0.y, s);
                s = fmaf(v0.z, v0.z, s); s = fmaf(v0.w, v0.w, s);
                s = fmaf(v1.x, v1.x, s); s = fmaf(v1.y, v1.y, s);
                s = fmaf(v1.z, v1.z, s); s = fmaf(v1.w, v1.w, s);
                __nv_bfloat162 p0 = __floats2bfloat162_rn(v0.x, v0.y);
                __nv_bfloat162 p1 = __floats2bfloat162_rn(v0.z, v0.w);
                __nv_bfloat162 p2 = __floats2bfloat162_rn(v1.x, v1.y);
                __nv_bfloat162 p3 = __floats2bfloat162_rn(v1.z, v1.w);
                uint4 u;
                u.x = *(uint32_t*)&p0; u.y = *(uint32_t*)&p1;
                u.z = *(uint32_t*)&p2; u.w = *(uint32_t*)&p3;
                *(uint4*)(dst + j * 16) = u;
            }
            e2[k] = s;
        }
    }
    __syncthreads();

    // ---- one-time: first 64 of this warp's codewords -> persistent B regs ----
    uint32_t breg[64];
    {
        const uint32_t bb0 = sb + SM_EMB
                           + (uint32_t)(128 * wid + (lane & 7)) * EPAD
                           + (uint32_t)(lane >> 3) * 16u;
        #pragma unroll
        for (int g = 0; g < 8; g++) {
            LDSM_X4(breg[g*8+0], breg[g*8+1], breg[g*8+2], breg[g*8+3],
                    bb0 + (uint32_t)g * (8u * EPAD));
            LDSM_X4(breg[g*8+4], breg[g*8+5], breg[g*8+6], breg[g*8+7],
                    bb0 + (uint32_t)g * (8u * EPAD) + 64u);
        }
    }

    const float* e2s = (const float*)(smem + SM_E2);
    const uint32_t bstr = sb + SM_EMB
                        + (uint32_t)(128 * wid + 64 + (lane & 7)) * EPAD
                        + (uint32_t)(lane >> 3) * 16u;

    for (;;) {
        if (tid == 0) work_sh = atomicAdd(&g_work, 1);
        __syncthreads();
        const int id = work_sh;
        if (id >= N_WORK) break;

        const int g3 = id / 3;
        const int r3 = id - 3 * g3;

        if (r3 < 2) {
            // ================= VQ tile =================
            const int tile = 2 * g3 + r3;
            const int b  = tile >> 7;
            const int n0 = (tile & 127) << 6;
            const float* zp = ze + (size_t)b * Q_DIM * N_DIM + n0;

            // ---- ze tile -> zeT[n][q] bf16 (STS.128) + exact fp32 ze2 ----
            {
                const int c  = tid & 63;     // column n
                const int jg = tid >> 6;     // 0/1: q in [32jg, 32jg+32)
                const float* zc = zp + c + (size_t)(32 * jg) * N_DIM;
                float z2 = 0.0f;
                char* dstr = smem + SM_ZET + c * EPAD + jg * 64;
                #pragma unroll
                for (int h = 0; h < 4; h++) {     // 8 q per chunk
                    float x0 = zc[(size_t)(8 * h + 0) * N_DIM];
                    float x1 = zc[(size_t)(8 * h + 1) * N_DIM];
                    float x2 = zc[(size_t)(8 * h + 2) * N_DIM];
                    float x3 = zc[(size_t)(8 * h + 3) * N_DIM];
                    float x4 = zc[(size_t)(8 * h + 4) * N_DIM];
                    float x5 = zc[(size_t)(8 * h + 5) * N_DIM];
                    float x6 = zc[(size_t)(8 * h + 6) * N_DIM];
                    float x7 = zc[(size_t)(8 * h + 7) * N_DIM];
                    z2 = fmaf(x0, x0, z2); z2 = fmaf(x1, x1, z2);
                    z2 = fmaf(x2, x2, z2); z2 = fmaf(x3, x3, z2);
                    z2 = fmaf(x4, x4, z2); z2 = fmaf(x5, x5, z2);
                    z2 = fmaf(x6, x6, z2); z2 = fmaf(x7, x7, z2);
                    __nv_bfloat162 p0 = __floats2bfloat162_rn(x0, x1);
                    __nv_bfloat162 p1 = __floats2bfloat162_rn(x2, x3);
                    __nv_bfloat162 p2 = __floats2bfloat162_rn(x4, x5);
                    __nv_bfloat162 p3 = __floats2bfloat162_rn(x6, x7);
                    uint4 u;
                    u.x = *(uint32_t*)&p0; u.y = *(uint32_t*)&p1;
                    u.z = *(uint32_t*)&p2; u.w = *(uint32_t*)&p3;
                    *(uint4*)(dstr + h * 16) = u;
                }
                z2s[jg * 64 + c] = z2;
            }
            __syncthreads();

            float vmin[4][2];
            #pragma unroll
            for (int s = 0; s < 4; s++) { vmin[s][0] = 3.4e38f; vmin[s][1] = 3.4e38f; }

            // ---- 4 A-sets streamed; per set: 8 reg-B groups + 8 streamed-B groups ----
            #pragma unroll
            for (int s = 0; s < 4; s++) {
                uint32_t a0[4], a1[4], a2[4], a3[4];
                uint32_t abase = sb + SM_ZET
                               + (uint32_t)(16 * s + (lane & 15)) * EPAD
                               + (uint32_t)(lane >> 4) * 16u;
                LDSM_X4(a0[0], a0[1], a0[2], a0[3], abase);
                LDSM_X4(a1[0], a1[1], a1[2], a1[3], abase + 32u);
                LDSM_X4(a2[0], a2[1], a2[2], a2[3], abase + 64u);
                LDSM_X4(a3[0], a3[1], a3[2], a3[3], abase + 96u);

                // register-resident B half (codewords 128w .. 128w+63)
                #pragma unroll
                for (int g = 0; g < 8; g++) {
                    float e0 = 0.f, e1 = 0.f, er2 = 0.f, e3 = 0.f;
                    float o0 = 0.f, o1 = 0.f, o2 = 0.f, o3 = 0.f;
                    MMA_BF16(a0[0], a0[1], a0[2], a0[3], breg[g*8+0], breg[g*8+1], e0, e1, er2, e3);
                    MMA_BF16(a1[0], a1[1], a1[2], a1[3], breg[g*8+2], breg[g*8+3], o0, o1, o2, o3);
                    MMA_BF16(a2[0], a2[1], a2[2], a2[3], breg[g*8+4], breg[g*8+5], e0, e1, er2, e3);
                    MMA_BF16(a3[0], a3[1], a3[2], a3[3], breg[g*8+6], breg[g*8+7], o0, o1, o2, o3);
                    float2 e2 = *(const float2*)(e2s + 128 * wid + g * 8 + 2 * (lane & 3));
                    float c0 = e0 + o0, c1 = e1 + o1, c2 = er2 + o2, c3 = e3 + o3;
                    vmin[s][0] = fminf(vmin[s][0],
                                       fminf(fmaf(-2.0f, c0, e2.x), fmaf(-2.0f, c1, e2.y)));
                    vmin[s][1] = fminf(vmin[s][1],
                                       fminf(fmaf(-2.0f, c2, e2.x), fmaf(-2.0f, c3, e2.y)));
                }
                // streamed B half (codewords 128w+64 .. 128w+127)
                #pragma unroll
                for (int g = 0; g < 8; g++) {
                    uint32_t bb[8];
                    LDSM_X4(bb[0], bb[1], bb[2], bb[3], bstr + (uint32_t)g * (8u * EPAD));
                    LDSM_X4(bb[4], bb[5], bb[6], bb[7], bstr + (uint32_t)g * (8u * EPAD) + 64u);
                    float e0 = 0.f, e1 = 0.f, er2 = 0.f, e3 = 0.f;
                    float o0 = 0.f, o1 = 0.f, o2 = 0.f, o3 = 0.f;
                    MMA_BF16(a0[0], a0[1], a0[2], a0[3], bb[0], bb[1], e0, e1, er2, e3);
                    MMA_BF16(a1[0], a1[1], a1[2], a1[3], bb[2], bb[3], o0, o1, o2, o3);
                    MMA_BF16(a2[0], a2[1], a2[2], a2[3], bb[4], bb[5], e0, e1, er2, e3);
                    MMA_BF16(a3[0], a3[1], a3[2], a3[3], bb[6], bb[7], o0, o1, o2, o3);
                    float2 e2 = *(const float2*)(e2s + 128 * wid + 64 + g * 8 + 2 * (lane & 3));
                    float c0 = e0 + o0, c1 = e1 + o1, c2 = er2 + o2, c3 = e3 + o3;
                    vmin[s][0] = fminf(vmin[s][0],
                                       fminf(fmaf(-2.0f, c0, e2.x), fmaf(-2.0f, c1, e2.y)));
                    vmin[s][1] = fminf(vmin[s][1],
                                       fminf(fmaf(-2.0f, c2, e2.x), fmaf(-2.0f, c3, e2.y)));
                }
            }

            // min across the 4 lanes of each row-quad
            #pragma unroll
            for (int s = 0; s < 4; s++) {
                #pragma unroll
                for (int h = 0; h < 2; h++) {
                    vmin[s][h] = fminf(vmin[s][h], __shfl_xor_sync(0xFFFFFFFFu, vmin[s][h], 1));
                    vmin[s][h] = fminf(vmin[s][h], __shfl_xor_sync(0xFFFFFFFFu, vmin[s][h], 2));
                }
            }
            if ((lane & 3) == 0) {
                int rr = lane >> 2;
                #pragma unroll
                for (int s = 0; s < 4; s++) {
                    wmin[wid * 64 + 16 * s + rr]     = vmin[s][0];
                    wmin[wid * 64 + 16 * s + rr + 8] = vmin[s][1];
                }
            }
            __syncthreads();

            if (wid == 0) {   // warp 0 combines all 64 n (2 per lane)
                float p = 0.0f;
                #pragma unroll
                for (int h = 0; h < 2; h++) {
                    int n = lane + 32 * h;
                    float m = fminf(fminf(wmin[n], wmin[64 + n]),
                                    fminf(wmin[128 + n], wmin[192 + n]));
                    float ze2 = z2s[n] + z2s[64 + n];
                    p += 1.25f * (m + ze2);
                }
                #pragma unroll
                for (int off = 16; off > 0; off >>= 1)
                    p += __shfl_down_sync(0xFFFFFFFFu, p, off);
                if (lane == 0) g_partials[tile] = p;
            }
        } else {
            // ================= REC tile (128 n-columns) =================
            const int rt = g3;                  // 0..511
            const int b  = rt >> 6;
            const int nt = rt & 63;
            const int n  = nt * 128 + tid;
            const float* base = qp + (size_t)b * C_DIM * N_DIM + n;

            float acc[8];
            #pragma unroll
            for (int j = 0; j < 8; j++) acc[j] = 0.0f;
            #pragma unroll 2
            for (int cc = 0; cc < C_DIM; cc += 16) {
                float x[16];
                #pragma unroll
                for (int j = 0; j < 16; j++)
                    x[j] = base[(size_t)(cc + j) * N_DIM];
                #pragma unroll
                for (int j = 0; j < 16; j++)
                    acc[j & 7] += __expf(x[j]);
            }
            float ssum = ((acc[0] + acc[1]) + (acc[2] + acc[3]))
                       + ((acc[4] + acc[5]) + (acc[6] + acc[7]));
            int t = tw[(size_t)b * N_DIM + n];
            t = min(max(t, 0), C_DIM - 1);
            float rec = __logf(ssum) - base[(size_t)t * N_DIM];

            #pragma unroll
            for (int off = 16; off > 0; off >>= 1)
                rec += __shfl_down_sync(0xFFFFFFFFu, rec, off);
            if (lane == 0) red[wid] = rec;
            __syncthreads();
            if (tid == 0)
                g_partials[N_VQ_TILES + rt] = (red[0] + red[1]) + (red[2] + red[3]);
        }
    }

    finalize(out);
}

// -------------------- launch --------------------
extern "C" void kernel_launch(void* const* d_in, const int* in_sizes, int n_in,
                              void* d_out, int out_size) {
    const float* ze  = (const float*)d_in[0];   // (B,Q,N)
    const float* emb = (const float*)d_in[1];   // (K,Q)
    const float* qp  = (const float*)d_in[2];   // (B,C,N)
    const int*   tw  = (const int*)d_in[3];     // (B,N) int32
    float* out = (float*)d_out;

    cudaFuncSetAttribute(fused_kernel, cudaFuncAttributeMaxDynamicSharedMemorySize,
                         SMEM_TOTAL);
    fused_kernel<<<GRID, THREADS, SMEM_TOTAL>>>(ze, emb, qp, tw, out);
}

// round 11
// speedup vs baseline: 1.5656x; 1.0085x over previous
#include <cuda_runtime.h>
#include <cuda_bf16.h>
#include <stdint.h>
#include <math.h>

#define B_DIM 8
#define Q_DIM 64
#define N_DIM 8192
#define K_DIM 512
#define C_DIM 256

#define GRID 296               // persistent CTAs (2 per SM)
#define THREADS 128
#define N_VQ_TILES 1024        // 64 n-columns each
#define N_REC_TILES 512        // 128 n-columns each
#define N_WORK (N_VQ_TILES + N_REC_TILES)   // 1536 = 512 groups of (2 vq + 1 rec)
#define NP N_WORK

__device__ float g_partials[NP];
__device__ int   g_arrived;
__device__ int   g_work;

// ---------------- smem layout (bytes) ----------------
#define EPAD 144               // 9 x 16B rows: conflict-free ldmatrix + STS.128
#define SM_RED   0             // 16B
#define SM_Z2    16            // 512B (2 half-sums per column)
#define SM_E2    528           // 2048B
#define SM_WMIN  2576          // 1024B ([4 warps][64 n])
#define SM_ZET   3600          // 64*144 = 9216B
#define SM_EMB   12816         // 512*144 = 73728B
#define SMEM_TOTAL 86544

// ---------------- helpers ----------------
__device__ __forceinline__ uint32_t smem_u32(const void* p) {
    uint32_t a;
    asm("{ .reg .u64 t; cvta.to.shared.u64 t, %1; cvt.u32.u64 %0, t; }" : "=r"(a) : "l"(p));
    return a;
}

#define LDSM_X4(r0, r1, r2, r3, addr) \
    asm volatile("ldmatrix.sync.aligned.m8n8.x4.shared.b16 {%0,%1,%2,%3}, [%4];" \
                 : "=r"(r0), "=r"(r1), "=r"(r2), "=r"(r3) : "r"(addr))

#define MMA_BF16(a0, a1, a2, a3, b0, b1, c0, c1, c2, c3) \
    asm volatile("mma.sync.aligned.m16n8k16.row.col.f32.bf16.bf16.f32 " \
                 "{%0,%1,%2,%3}, {%4,%5,%6,%7}, {%8,%9}, {%0,%1,%2,%3};" \
                 : "+f"(c0), "+f"(c1), "+f"(c2), "+f"(c3) \
                 : "r"(a0), "r"(a1), "r"(a2), "r"(a3), "r"(b0), "r"(b1))

// Last-arriving block sums all partials in a FIXED order -> bit-deterministic.
__device__ __forceinline__ void finalize(float* out) {
    __shared__ float fr[4];
    __shared__ int last;
    __threadfence();
    if (threadIdx.x == 0)
        last = (atomicAdd(&g_arrived, 1) == GRID - 1);
    __syncthreads();
    if (!last) return;
    __threadfence();
    float s = 0.0f;
    for (int i = threadIdx.x; i < NP; i += THREADS)
        s += g_partials[i];
    #pragma unroll
    for (int off = 16; off > 0; off >>= 1)
        s += __shfl_down_sync(0xFFFFFFFFu, s, off);
    if ((threadIdx.x & 31) == 0) fr[threadIdx.x >> 5] = s;
    __syncthreads();
    if (threadIdx.x == 0) {
        out[0] = ((fr[0] + fr[1]) + (fr[2] + fr[3]));
        g_arrived = 0;
        g_work = 0;
    }
}

// ==================== fused persistent kernel ====================
// 128 threads = 4 warps (256-reg budget). Warp w owns codewords
// [128w, 128w+128): 64 in persistent registers, 64 streamed ONCE per tile
// (applied to all 4 A-sets). All 4 A-sets (64 n-rows) held in registers.
__global__ __launch_bounds__(THREADS, 2) void fused_kernel(
    const float* __restrict__ ze, const float* __restrict__ emb,
    const float* __restrict__ qp, const int* __restrict__ tw,
    float* __restrict__ out)
{
    extern __shared__ char smem[];
    __shared__ int work_sh;
    const uint32_t sb = smem_u32(smem);
    const int tid  = threadIdx.x;
    const int lane = tid & 31;
    const int wid  = tid >> 5;        // 0..3

    float* red  = (float*)(smem + SM_RED);
    float* z2s  = (float*)(smem + SM_Z2);
    float* wmin = (float*)(smem + SM_WMIN);

    // ---- one-time: emb fp32 -> bf16 padded smem + ||emb||^2 ----
    {
        float* e2 = (float*)(smem + SM_E2);
        #pragma unroll
        for (int i = 0; i < K_DIM / THREADS; i++) {
            int k = tid + THREADS * i;
            const float4* src = (const float4*)(emb + (size_t)k * Q_DIM);
            char* dst = smem + SM_EMB + k * EPAD;
            float s = 0.0f;
            #pragma unroll
            for (int j = 0; j < 8; j++) {
                float4 v0 = src[2 * j];
                float4 v1 = src[2 * j + 1];
                s = fmaf(v0.x, v0.x, s); s = fmaf(v0.y, v0.y, s);
                s = fmaf(v0.z, v0.z, s); s = fmaf(v0.w, v0.w, s);
                s = fmaf(v1.x, v1.x, s); s = fmaf(v1.y, v1.y, s);
                s = fmaf(v1.z, v1.z, s); s = fmaf(v1.w, v1.w, s);
                __nv_bfloat162 p0 = __floats2bfloat162_rn(v0.x, v0.y);
                __nv_bfloat162 p1 = __floats2bfloat162_rn(v0.z, v0.w);
                __nv_bfloat162 p2 = __floats2bfloat162_rn(v1.x, v1.y);
                __nv_bfloat162 p3 = __floats2bfloat162_rn(v1.z, v1.w);
                uint4 u;
                u.x = *(uint32_t*)&p0; u.y = *(uint32_t*)&p1;
                u.z = *(uint32_t*)&p2; u.w = *(uint32_t*)&p3;
                *(uint4*)(dst + j * 16) = u;
            }
            e2[k] = s;
        }
    }
    __syncthreads();

    // ---- one-time: first 64 of this warp's codewords -> persistent B regs ----
    uint32_t breg[64];
    {
        const uint32_t bb0 = sb + SM_EMB
                           + (uint32_t)(128 * wid + (lane & 7)) * EPAD
                           + (uint32_t)(lane >> 3) * 16u;
        #pragma unroll
        for (int g = 0; g < 8; g++) {
            LDSM_X4(breg[g*8+0], breg[g*8+1], breg[g*8+2], breg[g*8+3],
                    bb0 + (uint32_t)g * (8u * EPAD));
            LDSM_X4(breg[g*8+4], breg[g*8+5], breg[g*8+6], breg[g*8+7],
                    bb0 + (uint32_t)g * (8u * EPAD) + 64u);
        }
    }

    const float* e2s = (const float*)(smem + SM_E2);
    const uint32_t bstr = sb + SM_EMB
                        + (uint32_t)(128 * wid + 64 + (lane & 7)) * EPAD
                        + (uint32_t)(lane >> 3) * 16u;

    for (;;) {
        if (tid == 0) work_sh = atomicAdd(&g_work, 1);
        __syncthreads();
        const int id = work_sh;
        if (id >= N_WORK) break;

        const int g3 = id / 3;
        const int r3 = id - 3 * g3;

        if (r3 < 2) {
            // ================= VQ tile =================
            const int tile = 2 * g3 + r3;
            const int b  = tile >> 7;
            const int n0 = (tile & 127) << 6;
            const float* zp = ze + (size_t)b * Q_DIM * N_DIM + n0;

            // ---- ze tile -> zeT[n][q] bf16 (STS.128) + exact fp32 ze2 ----
            {
                const int c  = tid & 63;     // column n
                const int jg = tid >> 6;     // 0/1: q in [32jg, 32jg+32)
                const float* zc = zp + c + (size_t)(32 * jg) * N_DIM;
                float z2 = 0.0f;
                char* dstr = smem + SM_ZET + c * EPAD + jg * 64;
                #pragma unroll
                for (int h = 0; h < 4; h++) {     // 8 q per chunk
                    float x0 = zc[(size_t)(8 * h + 0) * N_DIM];
                    float x1 = zc[(size_t)(8 * h + 1) * N_DIM];
                    float x2 = zc[(size_t)(8 * h + 2) * N_DIM];
                    float x3 = zc[(size_t)(8 * h + 3) * N_DIM];
                    float x4 = zc[(size_t)(8 * h + 4) * N_DIM];
                    float x5 = zc[(size_t)(8 * h + 5) * N_DIM];
                    float x6 = zc[(size_t)(8 * h + 6) * N_DIM];
                    float x7 = zc[(size_t)(8 * h + 7) * N_DIM];
                    z2 = fmaf(x0, x0, z2); z2 = fmaf(x1, x1, z2);
                    z2 = fmaf(x2, x2, z2); z2 = fmaf(x3, x3, z2);
                    z2 = fmaf(x4, x4, z2); z2 = fmaf(x5, x5, z2);
                    z2 = fmaf(x6, x6, z2); z2 = fmaf(x7, x7, z2);
                    __nv_bfloat162 p0 = __floats2bfloat162_rn(x0, x1);
                    __nv_bfloat162 p1 = __floats2bfloat162_rn(x2, x3);
                    __nv_bfloat162 p2 = __floats2bfloat162_rn(x4, x5);
                    __nv_bfloat162 p3 = __floats2bfloat162_rn(x6, x7);
                    uint4 u;
                    u.x = *(uint32_t*)&p0; u.y = *(uint32_t*)&p1;
                    u.z = *(uint32_t*)&p2; u.w = *(uint32_t*)&p3;
                    *(uint4*)(dstr + h * 16) = u;
                }
                z2s[jg * 64 + c] = z2;
            }
            __syncthreads();

            // ---- ALL 4 A-sets into registers (64 regs) ----
            uint32_t a[4][4][4];
            #pragma unroll
            for (int s = 0; s < 4; s++) {
                uint32_t abase = sb + SM_ZET
                               + (uint32_t)(16 * s + (lane & 15)) * EPAD
                               + (uint32_t)(lane >> 4) * 16u;
                #pragma unroll
                for (int ks = 0; ks < 4; ks++)
                    LDSM_X4(a[s][ks][0], a[s][ks][1], a[s][ks][2], a[s][ks][3],
                            abase + ks * 32u);
            }

            float vmin[4][2];
            #pragma unroll
            for (int s = 0; s < 4; s++) { vmin[s][0] = 3.4e38f; vmin[s][1] = 3.4e38f; }

            // ---- reg-resident B half: 8 groups x 4 sets x 4 MMAs ----
            #pragma unroll
            for (int g = 0; g < 8; g++) {
                float2 e2 = *(const float2*)(e2s + 128 * wid + g * 8 + 2 * (lane & 3));
                #pragma unroll
                for (int s = 0; s < 4; s++) {
                    float e0 = 0.f, e1 = 0.f, er2 = 0.f, e3 = 0.f;
                    float o0 = 0.f, o1 = 0.f, o2 = 0.f, o3 = 0.f;
                    MMA_BF16(a[s][0][0], a[s][0][1], a[s][0][2], a[s][0][3], breg[g*8+0], breg[g*8+1], e0, e1, er2, e3);
                    MMA_BF16(a[s][1][0], a[s][1][1], a[s][1][2], a[s][1][3], breg[g*8+2], breg[g*8+3], o0, o1, o2, o3);
                    MMA_BF16(a[s][2][0], a[s][2][1], a[s][2][2], a[s][2][3], breg[g*8+4], breg[g*8+5], e0, e1, er2, e3);
                    MMA_BF16(a[s][3][0], a[s][3][1], a[s][3][2], a[s][3][3], breg[g*8+6], breg[g*8+7], o0, o1, o2, o3);
                    float c0 = e0 + o0, c1 = e1 + o1, c2 = er2 + o2, c3 = e3 + o3;
                    vmin[s][0] = fminf(vmin[s][0],
                                       fminf(fmaf(-2.0f, c0, e2.x), fmaf(-2.0f, c1, e2.y)));
                    vmin[s][1] = fminf(vmin[s][1],
                                       fminf(fmaf(-2.0f, c2, e2.x), fmaf(-2.0f, c3, e2.y)));
                }
            }

            // ---- streamed B half: load each group ONCE, use for all 4 sets ----
            #pragma unroll
            for (int g = 0; g < 8; g++) {
                uint32_t bb[8];
                LDSM_X4(bb[0], bb[1], bb[2], bb[3], bstr + (uint32_t)g * (8u * EPAD));
                LDSM_X4(bb[4], bb[5], bb[6], bb[7], bstr + (uint32_t)g * (8u * EPAD) + 64u);
                float2 e2 = *(const float2*)(e2s + 128 * wid + 64 + g * 8 + 2 * (lane & 3));
                #pragma unroll
                for (int s = 0; s < 4; s++) {
                    float e0 = 0.f, e1 = 0.f, er2 = 0.f, e3 = 0.f;
                    float o0 = 0.f, o1 = 0.f, o2 = 0.f, o3 = 0.f;
                    MMA_BF16(a[s][0][0], a[s][0][1], a[s][0][2], a[s][0][3], bb[0], bb[1], e0, e1, er2, e3);
                    MMA_BF16(a[s][1][0], a[s][1][1], a[s][1][2], a[s][1][3], bb[2], bb[3], o0, o1, o2, o3);
                    MMA_BF16(a[s][2][0], a[s][2][1], a[s][2][2], a[s][2][3], bb[4], bb[5], e0, e1, er2, e3);
                    MMA_BF16(a[s][3][0], a[s][3][1], a[s][3][2], a[s][3][3], bb[6], bb[7], o0, o1, o2, o3);
                    float c0 = e0 + o0, c1 = e1 + o1, c2 = er2 + o2, c3 = e3 + o3;
                    vmin[s][0] = fminf(vmin[s][0],
                                       fminf(fmaf(-2.0f, c0, e2.x), fmaf(-2.0f, c1, e2.y)));
                    vmin[s][1] = fminf(vmin[s][1],
                                       fminf(fmaf(-2.0f, c2, e2.x), fmaf(-2.0f, c3, e2.y)));
                }
            }

            // min across the 4 lanes of each row-quad
            #pragma unroll
            for (int s = 0; s < 4; s++) {
                #pragma unroll
                for (int h = 0; h < 2; h++) {
                    vmin[s][h] = fminf(vmin[s][h], __shfl_xor_sync(0xFFFFFFFFu, vmin[s][h], 1));
                    vmin[s][h] = fminf(vmin[s][h], __shfl_xor_sync(0xFFFFFFFFu, vmin[s][h], 2));
                }
            }
            if ((lane & 3) == 0) {
                int rr = lane >> 2;
                #pragma unroll
                for (int s = 0; s < 4; s++) {
                    wmin[wid * 64 + 16 * s + rr]     = vmin[s][0];
                    wmin[wid * 64 + 16 * s + rr + 8] = vmin[s][1];
                }
            }
            __syncthreads();

            if (wid == 0) {   // warp 0 combines all 64 n (2 per lane)
                float p = 0.0f;
                #pragma unroll
                for (int h = 0; h < 2; h++) {
                    int n = lane + 32 * h;
                    float m = fminf(fminf(wmin[n], wmin[64 + n]),
                                    fminf(wmin[128 + n], wmin[192 + n]));
                    float ze2 = z2s[n] + z2s[64 + n];
                    p += 1.25f * (m + ze2);
                }
                #pragma unroll
                for (int off = 16; off > 0; off >>= 1)
                    p += __shfl_down_sync(0xFFFFFFFFu, p, off);
                if (lane == 0) g_partials[tile] = p;
            }
        } else {
            // ================= REC tile (128 n-columns) =================
            const int rt = g3;                  // 0..511
            const int b  = rt >> 6;
            const int nt = rt & 63;
            const int n  = nt * 128 + tid;
            const float* base = qp + (size_t)b * C_DIM * N_DIM + n;

            float acc[8];
            #pragma unroll
            for (int j = 0; j < 8; j++) acc[j] = 0.0f;
            #pragma unroll 2
            for (int cc = 0; cc < C_DIM; cc += 16) {
                float x[16];
                #pragma unroll
                for (int j = 0; j < 16; j++)
                    x[j] = base[(size_t)(cc + j) * N_DIM];
                #pragma unroll
                for (int j = 0; j < 16; j++)
                    acc[j & 7] += __expf(x[j]);
            }
            float ssum = ((acc[0] + acc[1]) + (acc[2] + acc[3]))
                       + ((acc[4] + acc[5]) + (acc[6] + acc[7]));
            int t = tw[(size_t)b * N_DIM + n];
            t = min(max(t, 0), C_DIM - 1);
            float rec = __logf(ssum) - base[(size_t)t * N_DIM];

            #pragma unroll
            for (int off = 16; off > 0; off >>= 1)
                rec += __shfl_down_sync(0xFFFFFFFFu, rec, off);
            if (lane == 0) red[wid] = rec;
            __syncthreads();
            if (tid == 0)
                g_partials[N_VQ_TILES + rt] = (red[0] + red[1]) + (red[2] + red[3]);
        }
    }

    finalize(out);
}

// -------------------- launch --------------------
extern "C" void kernel_launch(void* const* d_in, const int* in_sizes, int n_in,
                              void* d_out, int out_size) {
    const float* ze  = (const float*)d_in[0];   // (B,Q,N)
    const float* emb = (const float*)d_in[1];   // (K,Q)
    const float* qp  = (const float*)d_in[2];   // (B,C,N)
    const int*   tw  = (const int*)d_in[3];     // (B,N) int32
    float* out = (float*)d_out;

    cudaFuncSetAttribute(fused_kernel, cudaFuncAttributeMaxDynamicSharedMemorySize,
                         SMEM_TOTAL);
    fused_kernel<<<GRID, THREADS, SMEM_TOTAL>>>(ze, emb, qp, tw, out);
}